// round 1
// baseline (speedup 1.0000x reference)
#include <cuda_runtime.h>

#define BB 4
#define NN 512
#define DD 64
#define EPS 1e-5f
#define NEG_SLOPE 0.01f

// Scratch for per-row projections (allocation-free: __device__ globals)
__device__ float g_sq[BB * NN];
__device__ float g_sk[BB * NN];

// ---------------------------------------------------------------------------
// k1: per-row layernorm + sq/sk projections.
// One warp per row; each lane holds elements lane and lane+32 of the 64-wide row.
// blockDim = 256 (8 warps -> 8 rows), grid = B*N/8 = 256
// ---------------------------------------------------------------------------
__global__ void k1_ln_proj(const float* __restrict__ x,
                           const float* __restrict__ Wa,
                           const float* __restrict__ gamma,
                           const float* __restrict__ beta) {
    int row  = blockIdx.x * 8 + (threadIdx.x >> 5);
    int lane = threadIdx.x & 31;
    const float* r = x + (size_t)row * DD;

    float x0 = r[lane];
    float x1 = r[lane + 32];

    // mean
    float s = x0 + x1;
    #pragma unroll
    for (int o = 16; o; o >>= 1) s += __shfl_xor_sync(0xffffffffu, s, o);
    float mu = s * (1.0f / 64.0f);

    // variance
    float d0 = x0 - mu, d1 = x1 - mu;
    float v = d0 * d0 + d1 * d1;
    #pragma unroll
    for (int o = 16; o; o >>= 1) v += __shfl_xor_sync(0xffffffffu, v, o);
    float inv = rsqrtf(v * (1.0f / 64.0f) + EPS);

    float xn0 = d0 * inv * gamma[lane]      + beta[lane];
    float xn1 = d1 * inv * gamma[lane + 32] + beta[lane + 32];

    float sq = xn0 * Wa[lane]      + xn1 * Wa[lane + 32];
    float sk = xn0 * Wa[64 + lane] + xn1 * Wa[96 + lane];
    #pragma unroll
    for (int o = 16; o; o >>= 1) {
        sq += __shfl_xor_sync(0xffffffffu, sq, o);
        sk += __shfl_xor_sync(0xffffffffu, sk, o);
    }
    if (lane == 0) {
        g_sq[row] = sq;
        g_sk[row] = sk;
    }
}

// ---------------------------------------------------------------------------
// k2: alphas. One block (512 threads) per (b, i) row.
// score_j = sq[i] + sk[j] + b ; leaky relu ; softmax over j ; write alphas row.
// grid = B*N = 2048
// ---------------------------------------------------------------------------
__global__ void k2_softmax(const float* __restrict__ ba,
                           float* __restrict__ alphas) {
    int row = blockIdx.x;          // b*N + i
    int b   = row >> 9;            // row / 512
    int j   = threadIdx.x;         // 0..511
    int lane = j & 31, warp = j >> 5;

    __shared__ float red[16];

    float s = g_sq[row] + g_sk[b * NN + j] + ba[0];
    s = (s >= 0.0f) ? s : NEG_SLOPE * s;

    // --- block max ---
    float m = s;
    #pragma unroll
    for (int o = 16; o; o >>= 1) m = fmaxf(m, __shfl_xor_sync(0xffffffffu, m, o));
    if (lane == 0) red[warp] = m;
    __syncthreads();
    float bm = red[0];
    #pragma unroll
    for (int w = 1; w < 16; w++) bm = fmaxf(bm, red[w]);
    __syncthreads();

    // --- exp + block sum ---
    float e = __expf(s - bm);
    float t = e;
    #pragma unroll
    for (int o = 16; o; o >>= 1) t += __shfl_xor_sync(0xffffffffu, t, o);
    if (lane == 0) red[warp] = t;
    __syncthreads();
    float bs = red[0];
    #pragma unroll
    for (int w = 1; w < 16; w++) bs += red[w];

    alphas[(size_t)row * NN + j] = e * (1.0f / bs);
}

// ---------------------------------------------------------------------------
// k3: value[b,i,j,d] = i_em[b,i,d] * i_em[b,j,d]  -- the 256 MB store stream.
// One block (256 threads) per (b,i). Row i in smem. Each iteration a block
// covers 16 j's; thread layout: d4 = t&15 (float4 within row), jl = t>>4.
// A warp writes 512 contiguous bytes (2 full j-rows) -> perfectly coalesced.
// grid = B*N = 2048
// ---------------------------------------------------------------------------
__global__ void k3_value(const float* __restrict__ x,
                         float* __restrict__ value) {
    int bi = blockIdx.x;           // b*N + i
    int b  = bi >> 9;

    __shared__ float4 rowi[16];
    int t = threadIdx.x;
    if (t < 16) rowi[t] = ((const float4*)(x + (size_t)bi * DD))[t];
    __syncthreads();

    int d4 = t & 15;
    int jl = t >> 4;               // 0..15

    const float4* xb = (const float4*)(x + (size_t)b * NN * DD);
    float4*       o  = (float4*)(value + (size_t)bi * NN * DD);

    float4 a = rowi[d4];

    #pragma unroll 4
    for (int jc = 0; jc < NN; jc += 16) {
        int idx = (jc + jl) * 16 + d4;
        float4 v = xb[idx];        // L2-resident after first wave
        float4 r;
        r.x = a.x * v.x;
        r.y = a.y * v.y;
        r.z = a.z * v.z;
        r.w = a.w * v.w;
        o[idx] = r;
    }
}

// ---------------------------------------------------------------------------
extern "C" void kernel_launch(void* const* d_in, const int* in_sizes, int n_in,
                              void* d_out, int out_size) {
    const float* i_em  = (const float*)d_in[0];
    const float* W_a   = (const float*)d_in[1];
    const float* b_a   = (const float*)d_in[2];
    const float* gamma = (const float*)d_in[3];
    const float* beta  = (const float*)d_in[4];
    float* out = (float*)d_out;

    // output layout: alphas [B*N*N] then value [B*N*N*D]
    float* alphas = out;
    float* value  = out + (size_t)BB * NN * NN;

    k1_ln_proj<<<(BB * NN) / 8, 256>>>(i_em, W_a, gamma, beta);
    k2_softmax<<<BB * NN, 512>>>(b_a, alphas);
    k3_value<<<BB * NN, 256>>>(i_em, value);
}